// round 8
// baseline (speedup 1.0000x reference)
#include <cuda_runtime.h>
#include <math.h>

#define BSZ      131072
#define ROWS     64
#define NTHREADS 512
#define KT       64
#define SA       260   // stride for 256-wide activation buffers (mult of 4)
#define S3A      68    // stride for 64-wide a3/w3 buffer (mult of 4)
#define SW       258   // stride for staged weight tile rows (even; mod 32 = 2)

struct SmemLayout {
    float X[ROWS][4];
    float A1[ROWS * SA];
    float A2[ROWS * SA];
    float A3[ROWS * S3A];
    float WT[KT * SW];
    float Vpart[8][2][8];
    float Upart[8][2][8];
    float Gpart[8][2][8][4];
    float Grad[ROWS * 4];
    float Vv[ROWS];
    float Uu[ROWS];
};

typedef unsigned long long ull;

__device__ __forceinline__ ull dup2(float a) {
    ull r; unsigned int u = __float_as_uint(a);
    asm("mov.b64 %0, {%1, %1};" : "=l"(r) : "r"(u));
    return r;
}
__device__ __forceinline__ void unpack2(ull v, float& lo, float& hi) {
    unsigned int l, h;
    asm("mov.b64 {%0, %1}, %2;" : "=r"(l), "=r"(h) : "l"(v));
    lo = __uint_as_float(l); hi = __uint_as_float(h);
}
__device__ __forceinline__ void ffma2(ull& d, ull a, ull b) {
    asm("fma.rn.f32x2 %0, %1, %2, %0;" : "+l"(d) : "l"(a), "l"(b));
}

// ---------- N=256 GEMM, packed output-column pairs ----------
// Thread (rgrp = tid>>6, cgrp = tid&63) owns rows rgrp*8..+7 and column pairs
// n0 = 2*(cgrp + 64*m), m in {0,1}.  A warp shares one rgrp -> act loads are
// warp broadcasts; weight loads are lane-consecutive LDS.64.
// TRANSW=false: W is [256][ldw], stage W[n][k]   (forward: z = a @ W^T)
// TRANSW=true : W is [K][ldw],   stage W[k][n]   (backward: t = v @ W)
template <int K, bool TRANSW>
__device__ __forceinline__ void gemm256(const float* __restrict__ W, int ldw,
                                        const float* __restrict__ sA, int lda,
                                        float* __restrict__ sWT,
                                        ull (&acc)[8][2], int tid) {
    const int rgrp = tid >> 6;
    const int cgrp = tid & 63;
    for (int k0 = 0; k0 < K; k0 += KT) {
        __syncthreads();
        if (TRANSW) {
            #pragma unroll
            for (int idx = tid; idx < 256 * KT / 2; idx += NTHREADS) {
                int n2 = idx % 128;          // float2 index within row
                int kk = idx / 128;
                *reinterpret_cast<float2*>(&sWT[kk * SW + n2 * 2]) =
                    *reinterpret_cast<const float2*>(&W[(k0 + kk) * ldw + n2 * 2]);
            }
        } else {
            #pragma unroll
            for (int idx = tid; idx < 256 * KT; idx += NTHREADS) {
                int kk = idx % KT;           // consecutive tid -> consecutive kk
                int n  = idx / KT;
                sWT[kk * SW + n] = W[n * ldw + k0 + kk];
            }
        }
        __syncthreads();
        #pragma unroll 2
        for (int kq = 0; kq < KT / 4; kq++) {
            float4 av[8];
            #pragma unroll
            for (int i = 0; i < 8; i++)
                av[i] = *reinterpret_cast<const float4*>(
                            &sA[(rgrp * 8 + i) * lda + k0 + kq * 4]);
            #pragma unroll
            for (int q = 0; q < 4; q++) {
                ull ad[8];
                #pragma unroll
                for (int i = 0; i < 8; i++) {
                    float a = (q == 0) ? av[i].x : (q == 1) ? av[i].y
                            : (q == 2) ? av[i].z : av[i].w;
                    ad[i] = dup2(a);
                }
                const float* wrow = sWT + (kq * 4 + q) * SW;
                #pragma unroll
                for (int m = 0; m < 2; m++) {
                    ull w2 = *reinterpret_cast<const ull*>(
                                 &wrow[2 * (cgrp + 64 * m)]);
                    #pragma unroll
                    for (int i = 0; i < 8; i++)
                        ffma2(acc[i][m], ad[i], w2);
                }
            }
        }
    }
}

// ---------- N=64 GEMM (layer 3 forward), one scalar column per thread ----------
__device__ __forceinline__ void gemm64(const float* __restrict__ W, int ldw,
                                       const float* __restrict__ sA, int lda,
                                       float* __restrict__ sWT,
                                       float (&acc)[8], int tid) {
    const int rgrp = tid >> 6;
    const int cgrp = tid & 63;
    for (int k0 = 0; k0 < 256; k0 += KT) {
        __syncthreads();
        #pragma unroll
        for (int idx = tid; idx < 64 * KT; idx += NTHREADS) {
            int kk = idx % KT;
            int n  = idx / KT;
            sWT[kk * SW + n] = W[n * ldw + k0 + kk];
        }
        __syncthreads();
        #pragma unroll 2
        for (int kq = 0; kq < KT / 4; kq++) {
            float4 av[8];
            #pragma unroll
            for (int i = 0; i < 8; i++)
                av[i] = *reinterpret_cast<const float4*>(
                            &sA[(rgrp * 8 + i) * lda + k0 + kq * 4]);
            #pragma unroll
            for (int q = 0; q < 4; q++) {
                float w = sWT[(kq * 4 + q) * SW + cgrp];
                #pragma unroll
                for (int i = 0; i < 8; i++) {
                    float a = (q == 0) ? av[i].x : (q == 1) ? av[i].y
                            : (q == 2) ? av[i].z : av[i].w;
                    acc[i] = fmaf(a, w, acc[i]);
                }
            }
        }
    }
}

__device__ __forceinline__ float redux32(float v) {
    v += __shfl_xor_sync(0xffffffffu, v, 16);
    v += __shfl_xor_sync(0xffffffffu, v, 8);
    v += __shfl_xor_sync(0xffffffffu, v, 4);
    v += __shfl_xor_sync(0xffffffffu, v, 2);
    v += __shfl_xor_sync(0xffffffffu, v, 1);
    return v;
}

__global__ void __launch_bounds__(NTHREADS, 1)
clf_kernel(const float* __restrict__ x,
           const float* __restrict__ Vw1, const float* __restrict__ Vb1,
           const float* __restrict__ Vw2, const float* __restrict__ Vb2,
           const float* __restrict__ Vw3, const float* __restrict__ Vb3,
           const float* __restrict__ Uw1, const float* __restrict__ Ub1,
           const float* __restrict__ Uw2, const float* __restrict__ Ub2,
           const float* __restrict__ Uw3, const float* __restrict__ Ub3,
           float* __restrict__ out) {
    extern __shared__ char smem_raw[];
    SmemLayout& S = *reinterpret_cast<SmemLayout*>(smem_raw);
    const int tid  = threadIdx.x;
    const int rgrp = tid >> 6;
    const int cgrp = tid & 63;
    const int wh   = (tid >> 5) & 1;   // warp half within the 64-thread rgrp
    const int lane = tid & 31;
    const int base = blockIdx.x * ROWS;

    // ---- load x tile (64 x 4) ----
    if (tid < 256) {
        int b = tid >> 2, j = tid & 3;
        S.X[b][j] = x[(base + b) * 4 + j];
    }
    __syncthreads();

    // ---- a1 = tanh(x @ Vw1^T + Vb1); thread pair (unit, half) ----
    {
        int unit = tid >> 1, h = tid & 1;
        float4 w = *reinterpret_cast<const float4*>(&Vw1[unit * 4]);
        float bb = Vb1[unit];
        #pragma unroll 4
        for (int b = h * 32; b < h * 32 + 32; b++) {
            float z = fmaf(S.X[b][0], w.x, bb);
            z = fmaf(S.X[b][1], w.y, z);
            z = fmaf(S.X[b][2], w.z, z);
            z = fmaf(S.X[b][3], w.w, z);
            S.A1[b * SA + unit] = tanhf(z);
        }
    }

    // ---- a2 = tanh(a1 @ Vw2^T + Vb2) ----
    {
        ull acc[8][2];
        #pragma unroll
        for (int i = 0; i < 8; i++) { acc[i][0] = 0ull; acc[i][1] = 0ull; }
        gemm256<256, false>(Vw2, 256, S.A1, SA, S.WT, acc, tid);
        #pragma unroll
        for (int m = 0; m < 2; m++) {
            int n0 = 2 * (cgrp + 64 * m);
            float2 bb = *reinterpret_cast<const float2*>(&Vb2[n0]);
            #pragma unroll
            for (int i = 0; i < 8; i++) {
                float lo, hi; unpack2(acc[i][m], lo, hi);
                float2 r;
                r.x = tanhf(lo + bb.x);
                r.y = tanhf(hi + bb.y);
                *reinterpret_cast<float2*>(&S.A2[(rgrp * 8 + i) * SA + n0]) = r;
            }
        }
    }

    // ---- a3 = tanh(a2 @ Vw3^T + Vb3); V = 0.5*sum a3^2; A3 = a3*(1-a3^2) ----
    {
        float acc[8];
        #pragma unroll
        for (int i = 0; i < 8; i++) acc[i] = 0.f;
        gemm64(Vw3, 256, S.A2, SA, S.WT, acc, tid);
        float bb = Vb3[cgrp];
        float pV[8];
        #pragma unroll
        for (int i = 0; i < 8; i++) {
            float a3 = tanhf(acc[i] + bb);
            pV[i] = a3 * a3;
            S.A3[(rgrp * 8 + i) * S3A + cgrp] = a3 * (1.f - a3 * a3);
        }
        #pragma unroll
        for (int i = 0; i < 8; i++) {
            float v = redux32(pV[i]);
            if (lane == 0) S.Vpart[rgrp][wh][i] = v;
        }
    }

    // ---- t2' = (w3 @ Vw3) * (1 - a2^2), written in place into A2 ----
    {
        ull acc[8][2];
        #pragma unroll
        for (int i = 0; i < 8; i++) { acc[i][0] = 0ull; acc[i][1] = 0ull; }
        gemm256<64, true>(Vw3, 256, S.A3, S3A, S.WT, acc, tid);
        #pragma unroll
        for (int m = 0; m < 2; m++) {
            int n0 = 2 * (cgrp + 64 * m);
            #pragma unroll
            for (int i = 0; i < 8; i++) {
                int off = (rgrp * 8 + i) * SA + n0;
                float2 a2v = *reinterpret_cast<const float2*>(&S.A2[off]);
                float lo, hi; unpack2(acc[i][m], lo, hi);
                float2 r;
                r.x = lo * (1.f - a2v.x * a2v.x);
                r.y = hi * (1.f - a2v.y * a2v.y);
                *reinterpret_cast<float2*>(&S.A2[off]) = r;
            }
        }
    }

    // ---- t1' = (t2' @ Vw2) * (1 - a1^2);  grad_V = t1' @ Vw1 ----
    {
        ull acc[8][2];
        #pragma unroll
        for (int i = 0; i < 8; i++) { acc[i][0] = 0ull; acc[i][1] = 0ull; }
        gemm256<256, true>(Vw2, 256, S.A2, SA, S.WT, acc, tid);
        float gp[8][4];
        #pragma unroll
        for (int i = 0; i < 8; i++)
            #pragma unroll
            for (int j = 0; j < 4; j++) gp[i][j] = 0.f;
        #pragma unroll
        for (int m = 0; m < 2; m++) {
            int n0 = 2 * (cgrp + 64 * m);
            float4 wa = *reinterpret_cast<const float4*>(&Vw1[n0 * 4]);
            float4 wb = *reinterpret_cast<const float4*>(&Vw1[(n0 + 1) * 4]);
            #pragma unroll
            for (int i = 0; i < 8; i++) {
                float2 a1v = *reinterpret_cast<const float2*>(
                                 &S.A1[(rgrp * 8 + i) * SA + n0]);
                float lo, hi; unpack2(acc[i][m], lo, hi);
                float t1lo = lo * (1.f - a1v.x * a1v.x);
                float t1hi = hi * (1.f - a1v.y * a1v.y);
                gp[i][0] = fmaf(t1lo, wa.x, fmaf(t1hi, wb.x, gp[i][0]));
                gp[i][1] = fmaf(t1lo, wa.y, fmaf(t1hi, wb.y, gp[i][1]));
                gp[i][2] = fmaf(t1lo, wa.z, fmaf(t1hi, wb.z, gp[i][2]));
                gp[i][3] = fmaf(t1lo, wa.w, fmaf(t1hi, wb.w, gp[i][3]));
            }
        }
        #pragma unroll
        for (int i = 0; i < 8; i++)
            #pragma unroll
            for (int j = 0; j < 4; j++) {
                float v = redux32(gp[i][j]);
                if (lane == 0) S.Gpart[rgrp][wh][i][j] = v;
            }
    }
    __syncthreads();  // A1/Gpart/Vpart settled

    // combine cross-warp partials
    if (tid < 64) {
        int b = tid;
        S.Vv[b] = 0.5f * (S.Vpart[b >> 3][0][b & 7] + S.Vpart[b >> 3][1][b & 7]);
    } else if (tid >= 128 && tid < 384) {
        int t = tid - 128;
        int b = t >> 2, j = t & 3;
        S.Grad[b * 4 + j] =
            S.Gpart[b >> 3][0][b & 7][j] + S.Gpart[b >> 3][1][b & 7][j];
    }

    // ---- u1 = tanh(x @ Uw1^T + Ub1), overwrite A1 ----
    {
        int unit = tid >> 1, h = tid & 1;
        float4 w = *reinterpret_cast<const float4*>(&Uw1[unit * 4]);
        float bb = Ub1[unit];
        #pragma unroll 4
        for (int b = h * 32; b < h * 32 + 32; b++) {
            float z = fmaf(S.X[b][0], w.x, bb);
            z = fmaf(S.X[b][1], w.y, z);
            z = fmaf(S.X[b][2], w.z, z);
            z = fmaf(S.X[b][3], w.w, z);
            S.A1[b * SA + unit] = tanhf(z);
        }
    }

    // ---- u2 = tanh(u1 @ Uw2^T + Ub2); fold dot with Uw3 ----
    {
        ull acc[8][2];
        #pragma unroll
        for (int i = 0; i < 8; i++) { acc[i][0] = 0ull; acc[i][1] = 0ull; }
        gemm256<256, false>(Uw2, 256, S.A1, SA, S.WT, acc, tid);
        float pu[8];
        #pragma unroll
        for (int i = 0; i < 8; i++) pu[i] = 0.f;
        #pragma unroll
        for (int m = 0; m < 2; m++) {
            int n0 = 2 * (cgrp + 64 * m);
            float2 uw = *reinterpret_cast<const float2*>(&Uw3[n0]);
            float2 bb = *reinterpret_cast<const float2*>(&Ub2[n0]);
            #pragma unroll
            for (int i = 0; i < 8; i++) {
                float lo, hi; unpack2(acc[i][m], lo, hi);
                pu[i] = fmaf(tanhf(lo + bb.x), uw.x, pu[i]);
                pu[i] = fmaf(tanhf(hi + bb.y), uw.y, pu[i]);
            }
        }
        #pragma unroll
        for (int i = 0; i < 8; i++) {
            float v = redux32(pu[i]);
            if (lane == 0) S.Upart[rgrp][wh][i] = v;
        }
    }
    __syncthreads();

    // ---- per-row epilogue: dynamics + Vdot + writes ----
    if (tid < ROWS) {
        int b = tid;
        float uu = S.Upart[b >> 3][0][b & 7] + S.Upart[b >> 3][1][b & 7];
        float u = 20.f * tanhf(uu + Ub3[0]);
        float th = S.X[b][1], v = S.X[b][2], om = S.X[b][3];
        float s, c;
        sincosf(th, &s, &c);
        float den1 = c - 24.7f;
        float den2 = c * c - 24.7f;
        float f2 = (c * (9.8f * s + 11.5f * v) + 68.4f * v - 1.2f * om * om * s) / den1;
        float f3 = (-58.8f * v * c - 243.5f * v - s * (208.3f + om * om * c)) / den2;
        float g2 = (-1.8f * c - 10.9f) / den1;
        float g3 = (9.3f * c + 38.6f) / den2;
        float gv0 = S.Grad[b * 4 + 0], gv1 = S.Grad[b * 4 + 1];
        float gv2 = S.Grad[b * 4 + 2], gv3 = S.Grad[b * 4 + 3];
        float Lf = gv0 * v + gv1 * om + gv2 * f2 + gv3 * f3;
        float Lg = gv2 * g2 + gv3 * g3;
        int row = base + b;
        out[row]           = u;            // u  [BS,1]
        out[BSZ + row]     = S.Vv[b];      // V  [BS]
        out[2 * BSZ + row] = Lf + Lg * u;  // Vdot [BS,1,1]
    }
}

extern "C" void kernel_launch(void* const* d_in, const int* in_sizes, int n_in,
                              void* d_out, int out_size) {
    const float* x   = (const float*)d_in[0];
    const float* Vw1 = (const float*)d_in[1];
    const float* Vb1 = (const float*)d_in[2];
    const float* Vw2 = (const float*)d_in[3];
    const float* Vb2 = (const float*)d_in[4];
    const float* Vw3 = (const float*)d_in[5];
    const float* Vb3 = (const float*)d_in[6];
    const float* Uw1 = (const float*)d_in[7];
    const float* Ub1 = (const float*)d_in[8];
    const float* Uw2 = (const float*)d_in[9];
    const float* Ub2 = (const float*)d_in[10];
    const float* Uw3 = (const float*)d_in[11];
    const float* Ub3 = (const float*)d_in[12];
    float* out = (float*)d_out;

    cudaFuncSetAttribute(clf_kernel, cudaFuncAttributeMaxDynamicSharedMemorySize,
                         (int)sizeof(SmemLayout));
    clf_kernel<<<BSZ / ROWS, NTHREADS, sizeof(SmemLayout)>>>(
        x, Vw1, Vb1, Vw2, Vb2, Vw3, Vb3, Uw1, Ub1, Uw2, Ub2, Uw3, Ub3, out);
}

// round 11
// speedup vs baseline: 2.0960x; 2.0960x over previous
#include <cuda_runtime.h>
#include <cuda_bf16.h>
#include <math.h>

#define BSZ 131072
#define CR  128
#define NTH 512
#define SA  264   // activation plane stride (bf16 elems)
#define SW  72    // staged weight tile stride
#define SV3 264   // staged Vw3 stride

typedef unsigned int u32;
typedef unsigned short u16;

// ---------------- weight images (hi/lo bf16, natural layout) ----------------
__device__ __align__(16) u16 gVw2h[65536], gVw2l[65536];
__device__ __align__(16) u16 gUw2h[65536], gUw2l[65536];
__device__ __align__(16) u16 gVw3h[16384], gVw3l[16384];

__global__ void prep_kernel(const float* __restrict__ Vw2,
                            const float* __restrict__ Vw3,
                            const float* __restrict__ Uw2) {
    int i = blockIdx.x * blockDim.x + threadIdx.x;
    if (i >= 147456) return;
    float v; u16 *dh, *dl; int idx;
    if (i < 65536)       { idx = i;          v = Vw2[idx]; dh = gVw2h; dl = gVw2l; }
    else if (i < 131072) { idx = i - 65536;  v = Uw2[idx]; dh = gUw2h; dl = gUw2l; }
    else                 { idx = i - 131072; v = Vw3[idx]; dh = gVw3h; dl = gVw3l; }
    __nv_bfloat16 h = __float2bfloat16(v);
    dh[idx] = __bfloat16_as_ushort(h);
    dl[idx] = __bfloat16_as_ushort(__float2bfloat16(v - __bfloat162float(h)));
}

// ---------------- smem ----------------
struct Smem {
    u16 AH[CR * SA], AL[CR * SA];     // activation planes hi/lo
    u16 WH[18432], WL[18432];          // staged weight tile hi/lo
    float X[CR][4];
    float Vw1s[256][4], Uw1s[256][4];
    float Vb1s[256], Vb2s[256], Ub1s[256], Ub2s[256], Uw3s[256];
    float Vb3s[64];
    float Vpart[CR];
    float Upart[CR][2];
    float Gpart[CR][2][4];
};

// ---------------- helpers ----------------
__device__ __forceinline__ u32 s2u(const void* p) {
    u32 a; asm("{ .reg .u64 t; cvta.to.shared.u64 t, %1; cvt.u32.u64 %0, t; }"
               : "=r"(a) : "l"(p));
    return a;
}
__device__ __forceinline__ void ldsm4(u32& r0, u32& r1, u32& r2, u32& r3, u32 a) {
    asm volatile("ldmatrix.sync.aligned.m8n8.x4.shared.b16 {%0,%1,%2,%3}, [%4];"
                 : "=r"(r0), "=r"(r1), "=r"(r2), "=r"(r3) : "r"(a));
}
__device__ __forceinline__ void ldsm4t(u32& r0, u32& r1, u32& r2, u32& r3, u32 a) {
    asm volatile("ldmatrix.sync.aligned.m8n8.x4.trans.shared.b16 {%0,%1,%2,%3}, [%4];"
                 : "=r"(r0), "=r"(r1), "=r"(r2), "=r"(r3) : "r"(a));
}
__device__ __forceinline__ void mma4(float* c, u32 a0, u32 a1, u32 a2, u32 a3,
                                     u32 b0, u32 b1) {
    asm volatile("mma.sync.aligned.m16n8k16.row.col.f32.bf16.bf16.f32 "
                 "{%0,%1,%2,%3}, {%4,%5,%6,%7}, {%8,%9}, {%0,%1,%2,%3};"
                 : "+f"(c[0]), "+f"(c[1]), "+f"(c[2]), "+f"(c[3])
                 : "r"(a0), "r"(a1), "r"(a2), "r"(a3), "r"(b0), "r"(b1));
}
__device__ __forceinline__ void packp(float a, float b, u32& h, u32& l) {
    __nv_bfloat16 h0 = __float2bfloat16(a), h1 = __float2bfloat16(b);
    float r0 = a - __bfloat162float(h0), r1 = b - __bfloat162float(h1);
    h = (u32)__bfloat16_as_ushort(h0) | ((u32)__bfloat16_as_ushort(h1) << 16);
    l = (u32)__bfloat16_as_ushort(__float2bfloat16(r0)) |
        ((u32)__bfloat16_as_ushort(__float2bfloat16(r1)) << 16);
}

__device__ __forceinline__ void stageW(const u16* gh, const u16* gl,
                                       u16* WH, u16* WL, int s, int tid) {
    #pragma unroll 1
    for (int i = tid; i < 2048; i += NTH) {
        int row = i >> 3, u = i & 7;
        int gof = row * 256 + (s << 6) + u * 8;
        int sof = row * SW + u * 8;
        *(uint4*)&WH[sof] = *(const uint4*)&gh[gof];
        *(uint4*)&WL[sof] = *(const uint4*)&gl[gof];
    }
}
__device__ __forceinline__ void stageV3(const u16* gh, const u16* gl,
                                        u16* WH, u16* WL, int tid) {
    #pragma unroll 1
    for (int i = tid; i < 2048; i += NTH) {
        int row = i >> 5, u = i & 31;
        int gof = row * 256 + u * 8;
        int sof = row * SV3 + u * 8;
        *(uint4*)&WH[sof] = *(const uint4*)&gh[gof];
        *(uint4*)&WL[sof] = *(const uint4*)&gl[gof];
    }
}

// K=256, N=256 forward GEMM: acc[64] covers n = 128*nh .. +127 (16 n8 frags)
__device__ __forceinline__ void fwd256(const u16* gh, const u16* gl, float* acc,
                                       Smem& S, u32 smAH, u32 smAL,
                                       u32 smWH, u32 smWL,
                                       int tid, int lane, int nh, int R0) {
    u32 aoff = ((u32)((lane & 15) * SA + 8 * (lane >> 4))) * 2;
    int m = lane >> 3;
    u32 boff = ((u32)(((lane & 7) + 8 * (m >> 1)) * SW + 8 * (m & 1))) * 2;
    u32 aHb = smAH + (u32)(R0 * SA) * 2 + aoff;
    u32 aLb = smAL + (u32)(R0 * SA) * 2 + aoff;
    #pragma unroll 1
    for (int s = 0; s < 4; s++) {
        __syncthreads();
        stageW(gh, gl, S.WH, S.WL, s, tid);
        __syncthreads();
        #pragma unroll
        for (int q = 0; q < 4; q++) {
            int k = (s << 6) + (q << 4);
            u32 ah0, ah1, ah2, ah3, al0, al1, al2, al3;
            ldsm4(ah0, ah1, ah2, ah3, aHb + (u32)k * 2);
            ldsm4(al0, al1, al2, al3, aLb + (u32)k * 2);
            #pragma unroll
            for (int fp = 0; fp < 8; fp++) {
                int n0 = (nh << 7) + (fp << 4);
                u32 bb = (u32)(n0 * SW + (q << 4)) * 2;
                u32 bh0, bh1, bh2, bh3, bl0, bl1, bl2, bl3;
                ldsm4(bh0, bh1, bh2, bh3, smWH + boff + bb);
                ldsm4(bl0, bl1, bl2, bl3, smWL + boff + bb);
                float* c = acc + (fp << 3);
                mma4(c, ah0, ah1, ah2, ah3, bh0, bh1);
                mma4(c, al0, al1, al2, al3, bh0, bh1);
                mma4(c, ah0, ah1, ah2, ah3, bl0, bl1);
                mma4(c + 4, ah0, ah1, ah2, ah3, bh2, bh3);
                mma4(c + 4, al0, al1, al2, al3, bh2, bh3);
                mma4(c + 4, ah0, ah1, ah2, ah3, bl2, bl3);
            }
        }
    }
}

// layer-1: tanh(x @ W1^T + b) into planes. thread: 1 row x 64 cols
__device__ __forceinline__ void layer1w(Smem& S, const float (*W)[4],
                                        const float* bv, int tid) {
    int row = tid >> 2, cb = (tid & 3) << 6;
    float x0 = S.X[row][0], x1 = S.X[row][1], x2 = S.X[row][2], x3 = S.X[row][3];
    #pragma unroll 4
    for (int j = 0; j < 32; j++) {
        int col = cb + (j << 1);
        const float* w0 = W[col];
        const float* w1 = W[col + 1];
        float z0 = fmaf(x0, w0[0], fmaf(x1, w0[1], fmaf(x2, w0[2], fmaf(x3, w0[3], bv[col]))));
        float z1 = fmaf(x0, w1[0], fmaf(x1, w1[1], fmaf(x2, w1[2], fmaf(x3, w1[3], bv[col + 1]))));
        u32 h, l;
        packp(tanhf(z0), tanhf(z1), h, l);
        *(u32*)&S.AH[row * SA + col] = h;
        *(u32*)&S.AL[row * SA + col] = l;
    }
}

__global__ void __launch_bounds__(NTH, 1)
clf_mma(const float* __restrict__ x,
        const float* __restrict__ Vw1, const float* __restrict__ Vb1,
        const float* __restrict__ Vb2, const float* __restrict__ Vb3,
        const float* __restrict__ Uw1, const float* __restrict__ Ub1,
        const float* __restrict__ Ub2, const float* __restrict__ Uw3,
        const float* __restrict__ Ub3, float* __restrict__ out) {
    extern __shared__ char smraw[];
    Smem& S = *reinterpret_cast<Smem*>(smraw);
    const int tid = threadIdx.x, lane = tid & 31, wid = tid >> 5;
    const int mt = wid >> 1, nh = wid & 1;
    const int R0 = mt << 4;
    const int r4 = lane >> 2, c2 = (lane & 3) << 1;
    const int rowA = R0 + r4, rowB = rowA + 8;
    const int base = blockIdx.x * CR;

    // ---- parameter staging ----
    for (int i = tid; i < CR * 4; i += NTH) S.X[i >> 2][i & 3] = x[base * 4 + i];
    for (int i = tid; i < 1024; i += NTH) {
        ((float*)S.Vw1s)[i] = Vw1[i];
        ((float*)S.Uw1s)[i] = Uw1[i];
    }
    for (int i = tid; i < 256; i += NTH) {
        S.Vb1s[i] = Vb1[i]; S.Vb2s[i] = Vb2[i];
        S.Ub1s[i] = Ub1[i]; S.Ub2s[i] = Ub2[i]; S.Uw3s[i] = Uw3[i];
    }
    for (int i = tid; i < 64; i += NTH) S.Vb3s[i] = Vb3[i];
    __syncthreads();

    const u32 smAH = s2u(S.AH), smAL = s2u(S.AL);
    const u32 smWH = s2u(S.WH), smWL = s2u(S.WL);
    const int m = lane >> 3;

    // ---- a1 planes ----
    layer1w(S, S.Vw1s, S.Vb1s, tid);

    // ==== G1: a2 = tanh(a1 @ Vw2^T + b2) ====
    {
        float acc[64];
        #pragma unroll
        for (int i = 0; i < 64; i++) acc[i] = 0.f;
        fwd256(gVw2h, gVw2l, acc, S, smAH, smAL, smWH, smWL, tid, lane, nh, R0);
        __syncthreads();  // all a1-plane reads done before overwrite
        #pragma unroll
        for (int f = 0; f < 16; f++) {
            int n = (nh << 7) + (f << 3) + c2;
            float* c = acc + ((f >> 1) << 3) + ((f & 1) << 2);
            u32 h, l;
            packp(tanhf(c[0] + S.Vb2s[n]), tanhf(c[1] + S.Vb2s[n + 1]), h, l);
            *(u32*)&S.AH[rowA * SA + n] = h;
            *(u32*)&S.AL[rowA * SA + n] = l;
            packp(tanhf(c[2] + S.Vb2s[n]), tanhf(c[3] + S.Vb2s[n + 1]), h, l);
            *(u32*)&S.AH[rowB * SA + n] = h;
            *(u32*)&S.AL[rowB * SA + n] = l;
        }
    }

    // ==== G2: a3 = tanh(a2 @ Vw3^T + b3); V; w3 regs ====
    u32 w3h[16], w3l[16];
    {
        __syncthreads();
        stageV3(gVw3h, gVw3l, S.WH, S.WL, tid);
        __syncthreads();
        float a3c[32];
        #pragma unroll
        for (int i = 0; i < 32; i++) a3c[i] = 0.f;
        u32 aoff = ((u32)((lane & 15) * SA + 8 * (lane >> 4))) * 2;
        u32 aHb = smAH + (u32)(R0 * SA) * 2 + aoff;
        u32 aLb = smAL + (u32)(R0 * SA) * 2 + aoff;
        u32 boff3 = ((u32)(((lane & 7) + 8 * (m >> 1)) * SV3 + 8 * (m & 1))) * 2;
        #pragma unroll 1
        for (int q = 0; q < 16; q++) {
            u32 ah0, ah1, ah2, ah3, al0, al1, al2, al3;
            ldsm4(ah0, ah1, ah2, ah3, aHb + (u32)(q << 5));
            ldsm4(al0, al1, al2, al3, aLb + (u32)(q << 5));
            #pragma unroll
            for (int fp = 0; fp < 4; fp++) {
                u32 bb = (u32)((fp << 4) * SV3 + (q << 4)) * 2;
                u32 bh0, bh1, bh2, bh3, bl0, bl1, bl2, bl3;
                ldsm4(bh0, bh1, bh2, bh3, smWH + boff3 + bb);
                ldsm4(bl0, bl1, bl2, bl3, smWL + boff3 + bb);
                float* c = a3c + (fp << 3);
                mma4(c, ah0, ah1, ah2, ah3, bh0, bh1);
                mma4(c, al0, al1, al2, al3, bh0, bh1);
                mma4(c, ah0, ah1, ah2, ah3, bl0, bl1);
                mma4(c + 4, ah0, ah1, ah2, ah3, bh2, bh3);
                mma4(c + 4, al0, al1, al2, al3, bh2, bh3);
                mma4(c + 4, ah0, ah1, ah2, ah3, bl2, bl3);
            }
        }
        float pvA = 0.f, pvB = 0.f;
        #pragma unroll
        for (int f = 0; f < 8; f++) {
            int n = (f << 3) + c2;
            float* c = a3c + ((f >> 1) << 3) + ((f & 1) << 2);
            float v0 = tanhf(c[0] + S.Vb3s[n]);
            float v1 = tanhf(c[1] + S.Vb3s[n + 1]);
            float v2 = tanhf(c[2] + S.Vb3s[n]);
            float v3 = tanhf(c[3] + S.Vb3s[n + 1]);
            pvA += v0 * v0 + v1 * v1;
            pvB += v2 * v2 + v3 * v3;
            int bidx = ((f >> 1) << 2) + ((f & 1) << 1);
            packp(v0 * (1.f - v0 * v0), v1 * (1.f - v1 * v1), w3h[bidx], w3l[bidx]);
            packp(v2 * (1.f - v2 * v2), v3 * (1.f - v3 * v3), w3h[bidx + 1], w3l[bidx + 1]);
        }
        pvA += __shfl_xor_sync(0xffffffffu, pvA, 1);
        pvA += __shfl_xor_sync(0xffffffffu, pvA, 2);
        pvB += __shfl_xor_sync(0xffffffffu, pvB, 1);
        pvB += __shfl_xor_sync(0xffffffffu, pvB, 2);
        if ((lane & 3) == 0 && nh == 0) {
            S.Vpart[rowA] = pvA;
            S.Vpart[rowB] = pvB;
        }
    }

    // ==== G3: t2' = (w3 @ Vw3) * (1 - a2^2), planes overwritten in place ====
    {
        float t2c[64];
        #pragma unroll
        for (int i = 0; i < 64; i++) t2c[i] = 0.f;
        u32 boffB3 = ((u32)(((lane & 7) + 8 * (m & 1)) * SV3 + 8 * (m >> 1))) * 2;
        #pragma unroll
        for (int q = 0; q < 4; q++) {
            #pragma unroll
            for (int fp = 0; fp < 8; fp++) {
                int j0 = (nh << 7) + (fp << 4);
                u32 bb = (u32)((q << 4) * SV3 + j0) * 2;
                u32 bh0, bh1, bh2, bh3, bl0, bl1, bl2, bl3;
                ldsm4t(bh0, bh1, bh2, bh3, smWH + boffB3 + bb);
                ldsm4t(bl0, bl1, bl2, bl3, smWL + boffB3 + bb);
                float* c = t2c + (fp << 3);
                int a0 = q << 2;
                mma4(c, w3h[a0], w3h[a0 + 1], w3h[a0 + 2], w3h[a0 + 3], bh0, bh1);
                mma4(c, w3l[a0], w3l[a0 + 1], w3l[a0 + 2], w3l[a0 + 3], bh0, bh1);
                mma4(c, w3h[a0], w3h[a0 + 1], w3h[a0 + 2], w3h[a0 + 3], bl0, bl1);
                mma4(c + 4, w3h[a0], w3h[a0 + 1], w3h[a0 + 2], w3h[a0 + 3], bh2, bh3);
                mma4(c + 4, w3l[a0], w3l[a0 + 1], w3l[a0 + 2], w3l[a0 + 3], bh2, bh3);
                mma4(c + 4, w3h[a0], w3h[a0 + 1], w3h[a0 + 2], w3h[a0 + 3], bl2, bl3);
            }
        }
        // mask from a2 planes
        #pragma unroll
        for (int f = 0; f < 16; f++) {
            int n = (nh << 7) + (f << 3) + c2;
            float* c = t2c + ((f >> 1) << 3) + ((f & 1) << 2);
            u32 hA = *(u32*)&S.AH[rowA * SA + n];
            u32 lA = *(u32*)&S.AL[rowA * SA + n];
            u32 hB = *(u32*)&S.AH[rowB * SA + n];
            u32 lB = *(u32*)&S.AL[rowB * SA + n];
            float ax = __bfloat162float(__ushort_as_bfloat16((u16)(hA & 0xFFFF))) +
                       __bfloat162float(__ushort_as_bfloat16((u16)(lA & 0xFFFF)));
            float ay = __bfloat162float(__ushort_as_bfloat16((u16)(hA >> 16))) +
                       __bfloat162float(__ushort_as_bfloat16((u16)(lA >> 16)));
            float bx = __bfloat162float(__ushort_as_bfloat16((u16)(hB & 0xFFFF))) +
                       __bfloat162float(__ushort_as_bfloat16((u16)(lB & 0xFFFF)));
            float by = __bfloat162float(__ushort_as_bfloat16((u16)(hB >> 16))) +
                       __bfloat162float(__ushort_as_bfloat16((u16)(lB >> 16)));
            c[0] *= (1.f - ax * ax);
            c[1] *= (1.f - ay * ay);
            c[2] *= (1.f - bx * bx);
            c[3] *= (1.f - by * by);
        }
        __syncthreads();
        #pragma unroll
        for (int f = 0; f < 16; f++) {
            int n = (nh << 7) + (f << 3) + c2;
            float* c = t2c + ((f >> 1) << 3) + ((f & 1) << 2);
            u32 h, l;
            packp(c[0], c[1], h, l);
            *(u32*)&S.AH[rowA * SA + n] = h;
            *(u32*)&S.AL[rowA * SA + n] = l;
            packp(c[2], c[3], h, l);
            *(u32*)&S.AH[rowB * SA + n] = h;
            *(u32*)&S.AL[rowB * SA + n] = l;
        }
    }

    // ==== G4: t1' = (t2' @ Vw2)*(1-a1^2); grad_V = t1' @ Vw1 (folded) ====
    float gpA[4] = {0.f, 0.f, 0.f, 0.f}, gpB[4] = {0.f, 0.f, 0.f, 0.f};
    {
        float xa0 = S.X[rowA][0], xa1 = S.X[rowA][1], xa2 = S.X[rowA][2], xa3 = S.X[rowA][3];
        float xb0 = S.X[rowB][0], xb1 = S.X[rowB][1], xb2 = S.X[rowB][2], xb3 = S.X[rowB][3];
        u32 aoff = ((u32)((lane & 15) * SA + 8 * (lane >> 4))) * 2;
        u32 aHb = smAH + (u32)(R0 * SA) * 2 + aoff;
        u32 aLb = smAL + (u32)(R0 * SA) * 2 + aoff;
        u32 boffB = ((u32)(((lane & 7) + 8 * (m & 1)) * SW + 8 * (m >> 1))) * 2;
        #pragma unroll 1
        for (int s = 0; s < 4; s++) {
            __syncthreads();
            stageW(gVw2h, gVw2l, S.WH, S.WL, s, tid);
            __syncthreads();
            float c16[16];
            #pragma unroll
            for (int i = 0; i < 16; i++) c16[i] = 0.f;
            #pragma unroll 1
            for (int q = 0; q < 16; q++) {
                u32 ah0, ah1, ah2, ah3, al0, al1, al2, al3;
                ldsm4(ah0, ah1, ah2, ah3, aHb + (u32)(q << 5));
                ldsm4(al0, al1, al2, al3, aLb + (u32)(q << 5));
                #pragma unroll
                for (int fp = 0; fp < 2; fp++) {
                    int j0 = (nh << 5) + (fp << 4);
                    u32 bb = (u32)((q << 4) * SW + j0) * 2;
                    u32 bh0, bh1, bh2, bh3, bl0, bl1, bl2, bl3;
                    ldsm4t(bh0, bh1, bh2, bh3, smWH + boffB + bb);
                    ldsm4t(bl0, bl1, bl2, bl3, smWL + boffB + bb);
                    float* c = c16 + (fp << 3);
                    mma4(c, ah0, ah1, ah2, ah3, bh0, bh1);
                    mma4(c, al0, al1, al2, al3, bh0, bh1);
                    mma4(c, ah0, ah1, ah2, ah3, bl0, bl1);
                    mma4(c + 4, ah0, ah1, ah2, ah3, bh2, bh3);
                    mma4(c + 4, al0, al1, al2, al3, bh2, bh3);
                    mma4(c + 4, ah0, ah1, ah2, ah3, bl2, bl3);
                }
            }
            #pragma unroll
            for (int f = 0; f < 4; f++) {
                int n = (s << 6) + (nh << 5) + (f << 3) + c2;
                float* c = c16 + ((f >> 1) << 3) + ((f & 1) << 2);
                #pragma unroll
                for (int e = 0; e < 4; e++) {
                    int nn = n + (e & 1);
                    const float* w = S.Vw1s[nn];
                    float z, t;
                    if (e < 2)
                        z = fmaf(xa0, w[0], fmaf(xa1, w[1], fmaf(xa2, w[2], fmaf(xa3, w[3], S.Vb1s[nn]))));
                    else
                        z = fmaf(xb0, w[0], fmaf(xb1, w[1], fmaf(xb2, w[2], fmaf(xb3, w[3], S.Vb1s[nn]))));
                    float a1v = tanhf(z);
                    t = c[e] * (1.f - a1v * a1v);
                    float* gp = (e < 2) ? gpA : gpB;
                    gp[0] = fmaf(t, w[0], gp[0]);
                    gp[1] = fmaf(t, w[1], gp[1]);
                    gp[2] = fmaf(t, w[2], gp[2]);
                    gp[3] = fmaf(t, w[3], gp[3]);
                }
            }
        }
        #pragma unroll
        for (int j = 0; j < 4; j++) {
            gpA[j] += __shfl_xor_sync(0xffffffffu, gpA[j], 1);
            gpA[j] += __shfl_xor_sync(0xffffffffu, gpA[j], 2);
            gpB[j] += __shfl_xor_sync(0xffffffffu, gpB[j], 1);
            gpB[j] += __shfl_xor_sync(0xffffffffu, gpB[j], 2);
        }
        if ((lane & 3) == 0) {
            #pragma unroll
            for (int j = 0; j < 4; j++) {
                S.Gpart[rowA][nh][j] = gpA[j];
                S.Gpart[rowB][nh][j] = gpB[j];
            }
        }
    }

    // ==== G5: u1 planes + u2 GEMM + fold dot(Uw3) ====
    __syncthreads();
    layer1w(S, S.Uw1s, S.Ub1s, tid);
    {
        float acc[64];
        #pragma unroll
        for (int i = 0; i < 64; i++) acc[i] = 0.f;
        fwd256(gUw2h, gUw2l, acc, S, smAH, smAL, smWH, smWL, tid, lane, nh, R0);
        float puA = 0.f, puB = 0.f;
        #pragma unroll
        for (int f = 0; f < 16; f++) {
            int n = (nh << 7) + (f << 3) + c2;
            float* c = acc + ((f >> 1) << 3) + ((f & 1) << 2);
            puA = fmaf(tanhf(c[0] + S.Ub2s[n]), S.Uw3s[n], puA);
            puA = fmaf(tanhf(c[1] + S.Ub2s[n + 1]), S.Uw3s[n + 1], puA);
            puB = fmaf(tanhf(c[2] + S.Ub2s[n]), S.Uw3s[n], puB);
            puB = fmaf(tanhf(c[3] + S.Ub2s[n + 1]), S.Uw3s[n + 1], puB);
        }
        puA += __shfl_xor_sync(0xffffffffu, puA, 1);
        puA += __shfl_xor_sync(0xffffffffu, puA, 2);
        puB += __shfl_xor_sync(0xffffffffu, puB, 1);
        puB += __shfl_xor_sync(0xffffffffu, puB, 2);
        if ((lane & 3) == 0) {
            S.Upart[rowA][nh] = puA;
            S.Upart[rowB][nh] = puB;
        }
    }
    __syncthreads();

    // ==== final per-row epilogue ====
    if (tid < CR) {
        int b = tid;
        float V = 0.5f * S.Vpart[b];
        float uu = S.Upart[b][0] + S.Upart[b][1];
        float u = 20.f * tanhf(uu + Ub3[0]);
        float gv0 = S.Gpart[b][0][0] + S.Gpart[b][1][0];
        float gv1 = S.Gpart[b][0][1] + S.Gpart[b][1][1];
        float gv2 = S.Gpart[b][0][2] + S.Gpart[b][1][2];
        float gv3 = S.Gpart[b][0][3] + S.Gpart[b][1][3];
        float th = S.X[b][1], v = S.X[b][2], om = S.X[b][3];
        float s, c;
        sincosf(th, &s, &c);
        float den1 = c - 24.7f, den2 = c * c - 24.7f;
        float f2 = (c * (9.8f * s + 11.5f * v) + 68.4f * v - 1.2f * om * om * s) / den1;
        float f3 = (-58.8f * v * c - 243.5f * v - s * (208.3f + om * om * c)) / den2;
        float g2 = (-1.8f * c - 10.9f) / den1;
        float g3 = (9.3f * c + 38.6f) / den2;
        float Lf = gv0 * v + gv1 * om + gv2 * f2 + gv3 * f3;
        float Lg = gv2 * g2 + gv3 * g3;
        int r = base + b;
        out[r] = u;
        out[BSZ + r] = V;
        out[2 * BSZ + r] = Lf + Lg * u;
    }
}

extern "C" void kernel_launch(void* const* d_in, const int* in_sizes, int n_in,
                              void* d_out, int out_size) {
    const float* x   = (const float*)d_in[0];
    const float* Vw1 = (const float*)d_in[1];
    const float* Vb1 = (const float*)d_in[2];
    const float* Vw2 = (const float*)d_in[3];
    const float* Vb2 = (const float*)d_in[4];
    const float* Vw3 = (const float*)d_in[5];
    const float* Vb3 = (const float*)d_in[6];
    const float* Uw1 = (const float*)d_in[7];
    const float* Ub1 = (const float*)d_in[8];
    const float* Uw2 = (const float*)d_in[9];
    const float* Ub2 = (const float*)d_in[10];
    const float* Uw3 = (const float*)d_in[11];
    const float* Ub3 = (const float*)d_in[12];
    float* out = (float*)d_out;

    prep_kernel<<<288, 512>>>(Vw2, Vw3, Uw2);
    cudaFuncSetAttribute(clf_mma, cudaFuncAttributeMaxDynamicSharedMemorySize,
                         (int)sizeof(Smem));
    clf_mma<<<BSZ / CR, NTH, sizeof(Smem)>>>(
        x, Vw1, Vb1, Vb2, Vb3, Uw1, Ub1, Ub2, Uw3, Ub3, out);
}

// round 12
// speedup vs baseline: 2.5385x; 1.2111x over previous
#include <cuda_runtime.h>
#include <cuda_fp16.h>
#include <math.h>

#define BSZ 131072
#define CR  128
#define NTH 512
#define SA  264   // activation plane stride (half elems)
#define SW  72    // staged weight tile stride
#define SV3 264   // staged Vw3 stride

typedef unsigned int u32;
typedef unsigned short u16;

// ---------------- weight images (single half plane) ----------------
__device__ __align__(16) u16 gVw2s[65536];
__device__ __align__(16) u16 gUw2s[65536];
__device__ __align__(16) u16 gVw3s[16384];

__global__ void prep_kernel(const float* __restrict__ Vw2,
                            const float* __restrict__ Vw3,
                            const float* __restrict__ Uw2) {
    int i = blockIdx.x * blockDim.x + threadIdx.x;
    if (i >= 147456) return;
    float v; u16* dst; int idx;
    if (i < 65536)       { idx = i;          v = Vw2[idx]; dst = gVw2s; }
    else if (i < 131072) { idx = i - 65536;  v = Uw2[idx]; dst = gUw2s; }
    else                 { idx = i - 131072; v = Vw3[idx]; dst = gVw3s; }
    dst[idx] = __half_as_ushort(__float2half_rn(v));
}

// ---------------- smem ----------------
struct Smem {
    u16 AH[CR * SA], AL[CR * SA];   // activation planes hi/lo (half)
    u16 WH[18432];                  // staged weight tile (single plane)
    float X[CR][4];
    float Vw1s[256][4], Uw1s[256][4];
    float Vb1s[256], Vb2s[256], Ub1s[256], Ub2s[256], Uw3s[256];
    float Vb3s[64];
    float Vpart[CR];
    float Upart[CR][4];
    float Gpart[CR][2][4];
};

// ---------------- helpers ----------------
__device__ __forceinline__ u32 s2u(const void* p) {
    u32 a; asm("{ .reg .u64 t; cvta.to.shared.u64 t, %1; cvt.u32.u64 %0, t; }"
               : "=r"(a) : "l"(p));
    return a;
}
__device__ __forceinline__ void ldsm4(u32& r0, u32& r1, u32& r2, u32& r3, u32 a) {
    asm volatile("ldmatrix.sync.aligned.m8n8.x4.shared.b16 {%0,%1,%2,%3}, [%4];"
                 : "=r"(r0), "=r"(r1), "=r"(r2), "=r"(r3) : "r"(a));
}
__device__ __forceinline__ void ldsm4t(u32& r0, u32& r1, u32& r2, u32& r3, u32 a) {
    asm volatile("ldmatrix.sync.aligned.m8n8.x4.trans.shared.b16 {%0,%1,%2,%3}, [%4];"
                 : "=r"(r0), "=r"(r1), "=r"(r2), "=r"(r3) : "r"(a));
}
__device__ __forceinline__ void mma4(float* c, u32 a0, u32 a1, u32 a2, u32 a3,
                                     u32 b0, u32 b1) {
    asm volatile("mma.sync.aligned.m16n8k16.row.col.f32.f16.f16.f32 "
                 "{%0,%1,%2,%3}, {%4,%5,%6,%7}, {%8,%9}, {%0,%1,%2,%3};"
                 : "+f"(c[0]), "+f"(c[1]), "+f"(c[2]), "+f"(c[3])
                 : "r"(a0), "r"(a1), "r"(a2), "r"(a3), "r"(b0), "r"(b1));
}
__device__ __forceinline__ void packp(float a, float b, u32& h, u32& l) {
    __half h0 = __float2half_rn(a), h1 = __float2half_rn(b);
    float r0 = a - __half2float(h0), r1 = b - __half2float(h1);
    h = (u32)__half_as_ushort(h0) | ((u32)__half_as_ushort(h1) << 16);
    l = (u32)__half_as_ushort(__float2half_rn(r0)) |
        ((u32)__half_as_ushort(__float2half_rn(r1)) << 16);
}
__device__ __forceinline__ float hlo(u32 v) {
    return __half2float(__ushort_as_half((u16)(v & 0xFFFF)));
}
__device__ __forceinline__ float hhi(u32 v) {
    return __half2float(__ushort_as_half((u16)(v >> 16)));
}

__device__ __forceinline__ void stageWh(const u16* gw, u16* WH, int s, int tid) {
    #pragma unroll 1
    for (int i = tid; i < 2048; i += NTH) {
        int row = i >> 3, u = i & 7;
        *(uint4*)&WH[row * SW + u * 8] =
            *(const uint4*)&gw[row * 256 + (s << 6) + u * 8];
    }
}
__device__ __forceinline__ void stageV3h(const u16* gw, u16* WH, int tid) {
    #pragma unroll 1
    for (int i = tid; i < 2048; i += NTH) {
        int row = i >> 5, u = i & 31;
        *(uint4*)&WH[row * SV3 + u * 8] =
            *(const uint4*)&gw[row * 256 + u * 8];
    }
}

// K=256, N=256 forward GEMM, M=32 per warp (2 sub-tiles), N=64 (4 frag pairs)
__device__ __forceinline__ void fwd256h(const u16* gw, float* acc, Smem& S,
                                        u32 smAH, u32 smAL, u32 smWH,
                                        int tid, int lane, int nq, int R0) {
    u32 aoff = ((u32)((lane & 15) * SA + 8 * (lane >> 4))) * 2;
    int m = lane >> 3;
    u32 boff = ((u32)(((lane & 7) + 8 * (m >> 1)) * SW + 8 * (m & 1))) * 2;
    u32 aHb = smAH + (u32)(R0 * SA) * 2 + aoff;
    u32 aLb = smAL + (u32)(R0 * SA) * 2 + aoff;
    #pragma unroll 1
    for (int s = 0; s < 4; s++) {
        __syncthreads();
        stageWh(gw, S.WH, s, tid);
        __syncthreads();
        #pragma unroll
        for (int q = 0; q < 4; q++) {
            int k = (s << 6) + (q << 4);
            u32 ah[2][4], al[2][4];
            #pragma unroll
            for (int sub = 0; sub < 2; sub++) {
                u32 sof = (u32)(sub * 16 * SA + k) * 2;
                ldsm4(ah[sub][0], ah[sub][1], ah[sub][2], ah[sub][3], aHb + sof);
                ldsm4(al[sub][0], al[sub][1], al[sub][2], al[sub][3], aLb + sof);
            }
            #pragma unroll
            for (int fp = 0; fp < 4; fp++) {
                int n0 = (nq << 6) + (fp << 4);
                u32 bb = (u32)(n0 * SW + (q << 4)) * 2;
                u32 b0, b1, b2, b3;
                ldsm4(b0, b1, b2, b3, smWH + boff + bb);
                #pragma unroll
                for (int sub = 0; sub < 2; sub++) {
                    float* c = acc + (((sub << 2) + fp) << 3);
                    mma4(c, ah[sub][0], ah[sub][1], ah[sub][2], ah[sub][3], b0, b1);
                    mma4(c, al[sub][0], al[sub][1], al[sub][2], al[sub][3], b0, b1);
                    mma4(c + 4, ah[sub][0], ah[sub][1], ah[sub][2], ah[sub][3], b2, b3);
                    mma4(c + 4, al[sub][0], al[sub][1], al[sub][2], al[sub][3], b2, b3);
                }
            }
        }
    }
}

// layer-1: tanh(x @ W1^T + b) into half planes. thread: 1 row x 64 cols
__device__ __forceinline__ void layer1w(Smem& S, const float (*W)[4],
                                        const float* bv, int tid) {
    int row = tid >> 2, cb = (tid & 3) << 6;
    float x0 = S.X[row][0], x1 = S.X[row][1], x2 = S.X[row][2], x3 = S.X[row][3];
    #pragma unroll 4
    for (int j = 0; j < 32; j++) {
        int col = cb + (j << 1);
        const float* w0 = W[col];
        const float* w1 = W[col + 1];
        float z0 = fmaf(x0, w0[0], fmaf(x1, w0[1], fmaf(x2, w0[2], fmaf(x3, w0[3], bv[col]))));
        float z1 = fmaf(x0, w1[0], fmaf(x1, w1[1], fmaf(x2, w1[2], fmaf(x3, w1[3], bv[col + 1]))));
        u32 h, l;
        packp(tanhf(z0), tanhf(z1), h, l);
        *(u32*)&S.AH[row * SA + col] = h;
        *(u32*)&S.AL[row * SA + col] = l;
    }
}

__global__ void __launch_bounds__(NTH, 1)
clf_mma(const float* __restrict__ x,
        const float* __restrict__ Vw1, const float* __restrict__ Vb1,
        const float* __restrict__ Vb2, const float* __restrict__ Vb3,
        const float* __restrict__ Uw1, const float* __restrict__ Ub1,
        const float* __restrict__ Ub2, const float* __restrict__ Uw3,
        const float* __restrict__ Ub3, float* __restrict__ out) {
    extern __shared__ char smraw[];
    Smem& S = *reinterpret_cast<Smem*>(smraw);
    const int tid = threadIdx.x, lane = tid & 31, wid = tid >> 5;
    // new mapping (big GEMMs): 4 M-tiles x 4 N-quarters
    const int nq = wid & 3, R0n = (wid >> 2) << 5;
    // old mapping (G2/G3/G4): 8 M-tiles x 2 N-halves
    const int nh = wid & 1, R0o = (wid >> 1) << 4;
    const int r4 = lane >> 2, c2 = (lane & 3) << 1, m = lane >> 3;
    const int rowAo = R0o + r4, rowBo = rowAo + 8;
    const int base = blockIdx.x * CR;

    // ---- parameter staging ----
    for (int i = tid; i < CR * 4; i += NTH) S.X[i >> 2][i & 3] = x[base * 4 + i];
    for (int i = tid; i < 1024; i += NTH) {
        ((float*)S.Vw1s)[i] = Vw1[i];
        ((float*)S.Uw1s)[i] = Uw1[i];
    }
    for (int i = tid; i < 256; i += NTH) {
        S.Vb1s[i] = Vb1[i]; S.Vb2s[i] = Vb2[i];
        S.Ub1s[i] = Ub1[i]; S.Ub2s[i] = Ub2[i]; S.Uw3s[i] = Uw3[i];
    }
    for (int i = tid; i < 64; i += NTH) S.Vb3s[i] = Vb3[i];
    __syncthreads();

    const u32 smAH = s2u(S.AH), smAL = s2u(S.AL), smWH = s2u(S.WH);

    // ---- a1 planes ----
    layer1w(S, S.Vw1s, S.Vb1s, tid);

    // ==== G1: a2 = tanh(a1 @ Vw2^T + b2) ====
    {
        float acc[64];
        #pragma unroll
        for (int i = 0; i < 64; i++) acc[i] = 0.f;
        fwd256h(gVw2s, acc, S, smAH, smAL, smWH, tid, lane, nq, R0n);
        __syncthreads();  // all a1-plane reads done before overwrite
        #pragma unroll
        for (int sub = 0; sub < 2; sub++) {
            int rA = R0n + (sub << 4) + r4, rB = rA + 8;
            #pragma unroll
            for (int fp = 0; fp < 4; fp++) {
                float* c = acc + (((sub << 2) + fp) << 3);
                #pragma unroll
                for (int h2 = 0; h2 < 2; h2++) {
                    int n = (nq << 6) + (fp << 4) + (h2 << 3) + c2;
                    u32 h, l;
                    packp(tanhf(c[h2 * 4 + 0] + S.Vb2s[n]),
                          tanhf(c[h2 * 4 + 1] + S.Vb2s[n + 1]), h, l);
                    *(u32*)&S.AH[rA * SA + n] = h;
                    *(u32*)&S.AL[rA * SA + n] = l;
                    packp(tanhf(c[h2 * 4 + 2] + S.Vb2s[n]),
                          tanhf(c[h2 * 4 + 3] + S.Vb2s[n + 1]), h, l);
                    *(u32*)&S.AH[rB * SA + n] = h;
                    *(u32*)&S.AL[rB * SA + n] = l;
                }
            }
        }
    }

    // ==== G2: a3 = tanh(a2 @ Vw3^T + b3); V; w3 regs ====  (old mapping)
    u32 w3h[16], w3l[16];
    {
        __syncthreads();
        stageV3h(gVw3s, S.WH, tid);
        __syncthreads();
        float a3c[32];
        #pragma unroll
        for (int i = 0; i < 32; i++) a3c[i] = 0.f;
        u32 aoff = ((u32)((lane & 15) * SA + 8 * (lane >> 4))) * 2;
        u32 aHb = smAH + (u32)(R0o * SA) * 2 + aoff;
        u32 aLb = smAL + (u32)(R0o * SA) * 2 + aoff;
        u32 boff3 = ((u32)(((lane & 7) + 8 * (m >> 1)) * SV3 + 8 * (m & 1))) * 2;
        #pragma unroll 1
        for (int q = 0; q < 16; q++) {
            u32 ah0, ah1, ah2, ah3, al0, al1, al2, al3;
            ldsm4(ah0, ah1, ah2, ah3, aHb + (u32)(q << 5));
            ldsm4(al0, al1, al2, al3, aLb + (u32)(q << 5));
            #pragma unroll
            for (int fp = 0; fp < 4; fp++) {
                u32 bb = (u32)((fp << 4) * SV3 + (q << 4)) * 2;
                u32 b0, b1, b2, b3;
                ldsm4(b0, b1, b2, b3, smWH + boff3 + bb);
                float* c = a3c + (fp << 3);
                mma4(c, ah0, ah1, ah2, ah3, b0, b1);
                mma4(c, al0, al1, al2, al3, b0, b1);
                mma4(c + 4, ah0, ah1, ah2, ah3, b2, b3);
                mma4(c + 4, al0, al1, al2, al3, b2, b3);
            }
        }
        float pvA = 0.f, pvB = 0.f;
        #pragma unroll
        for (int f = 0; f < 8; f++) {
            int n = (f << 3) + c2;
            float* c = a3c + ((f >> 1) << 3) + ((f & 1) << 2);
            float v0 = tanhf(c[0] + S.Vb3s[n]);
            float v1 = tanhf(c[1] + S.Vb3s[n + 1]);
            float v2 = tanhf(c[2] + S.Vb3s[n]);
            float v3 = tanhf(c[3] + S.Vb3s[n + 1]);
            pvA += v0 * v0 + v1 * v1;
            pvB += v2 * v2 + v3 * v3;
            int bidx = ((f >> 1) << 2) + ((f & 1) << 1);
            packp(v0 * (1.f - v0 * v0), v1 * (1.f - v1 * v1), w3h[bidx], w3l[bidx]);
            packp(v2 * (1.f - v2 * v2), v3 * (1.f - v3 * v3), w3h[bidx + 1], w3l[bidx + 1]);
        }
        pvA += __shfl_xor_sync(0xffffffffu, pvA, 1);
        pvA += __shfl_xor_sync(0xffffffffu, pvA, 2);
        pvB += __shfl_xor_sync(0xffffffffu, pvB, 1);
        pvB += __shfl_xor_sync(0xffffffffu, pvB, 2);
        if ((lane & 3) == 0 && nh == 0) {
            S.Vpart[rowAo] = pvA;
            S.Vpart[rowBo] = pvB;
        }
    }

    // ==== G3: t2' = (w3 @ Vw3) * (1 - a2^2), planes overwritten in place ====
    {
        float t2c[64];
        #pragma unroll
        for (int i = 0; i < 64; i++) t2c[i] = 0.f;
        u32 boffB3 = ((u32)(((lane & 7) + 8 * (m & 1)) * SV3 + 8 * (m >> 1))) * 2;
        #pragma unroll
        for (int q = 0; q < 4; q++) {
            int a0 = q << 2;
            #pragma unroll
            for (int fp = 0; fp < 8; fp++) {
                int j0 = (nh << 7) + (fp << 4);
                u32 bb = (u32)((q << 4) * SV3 + j0) * 2;
                u32 b0, b1, b2, b3;
                ldsm4t(b0, b1, b2, b3, smWH + boffB3 + bb);
                float* c = t2c + (fp << 3);
                mma4(c, w3h[a0], w3h[a0 + 1], w3h[a0 + 2], w3h[a0 + 3], b0, b1);
                mma4(c, w3l[a0], w3l[a0 + 1], w3l[a0 + 2], w3l[a0 + 3], b0, b1);
                mma4(c + 4, w3h[a0], w3h[a0 + 1], w3h[a0 + 2], w3h[a0 + 3], b2, b3);
                mma4(c + 4, w3l[a0], w3l[a0 + 1], w3l[a0 + 2], w3l[a0 + 3], b2, b3);
            }
        }
        // mask from a2 planes
        #pragma unroll
        for (int f = 0; f < 16; f++) {
            int n = (nh << 7) + (f << 3) + c2;
            float* c = t2c + ((f >> 1) << 3) + ((f & 1) << 2);
            u32 hA = *(u32*)&S.AH[rowAo * SA + n];
            u32 lA = *(u32*)&S.AL[rowAo * SA + n];
            u32 hB = *(u32*)&S.AH[rowBo * SA + n];
            u32 lB = *(u32*)&S.AL[rowBo * SA + n];
            float ax = hlo(hA) + hlo(lA), ay = hhi(hA) + hhi(lA);
            float bx = hlo(hB) + hlo(lB), by = hhi(hB) + hhi(lB);
            c[0] *= (1.f - ax * ax);
            c[1] *= (1.f - ay * ay);
            c[2] *= (1.f - bx * bx);
            c[3] *= (1.f - by * by);
        }
        __syncthreads();
        #pragma unroll
        for (int f = 0; f < 16; f++) {
            int n = (nh << 7) + (f << 3) + c2;
            float* c = t2c + ((f >> 1) << 3) + ((f & 1) << 2);
            u32 h, l;
            packp(c[0], c[1], h, l);
            *(u32*)&S.AH[rowAo * SA + n] = h;
            *(u32*)&S.AL[rowAo * SA + n] = l;
            packp(c[2], c[3], h, l);
            *(u32*)&S.AH[rowBo * SA + n] = h;
            *(u32*)&S.AL[rowBo * SA + n] = l;
        }
    }

    // ==== G4: t1' = (t2' @ Vw2)*(1-a1^2); grad_V = t1' @ Vw1 (folded) ====
    float gpA[4] = {0.f, 0.f, 0.f, 0.f}, gpB[4] = {0.f, 0.f, 0.f, 0.f};
    {
        float xa0 = S.X[rowAo][0], xa1 = S.X[rowAo][1], xa2 = S.X[rowAo][2], xa3 = S.X[rowAo][3];
        float xb0 = S.X[rowBo][0], xb1 = S.X[rowBo][1], xb2 = S.X[rowBo][2], xb3 = S.X[rowBo][3];
        u32 aoff = ((u32)((lane & 15) * SA + 8 * (lane >> 4))) * 2;
        u32 aHb = smAH + (u32)(R0o * SA) * 2 + aoff;
        u32 aLb = smAL + (u32)(R0o * SA) * 2 + aoff;
        u32 boffB = ((u32)(((lane & 7) + 8 * (m & 1)) * SW + 8 * (m >> 1))) * 2;
        #pragma unroll 1
        for (int s = 0; s < 4; s++) {
            __syncthreads();
            stageWh(gVw2s, S.WH, s, tid);
            __syncthreads();
            float c16[16];
            #pragma unroll
            for (int i = 0; i < 16; i++) c16[i] = 0.f;
            #pragma unroll 1
            for (int q = 0; q < 16; q++) {
                u32 ah0, ah1, ah2, ah3, al0, al1, al2, al3;
                ldsm4(ah0, ah1, ah2, ah3, aHb + (u32)(q << 5));
                ldsm4(al0, al1, al2, al3, aLb + (u32)(q << 5));
                #pragma unroll
                for (int fp = 0; fp < 2; fp++) {
                    int j0 = (nh << 5) + (fp << 4);
                    u32 bb = (u32)((q << 4) * SW + j0) * 2;
                    u32 b0, b1, b2, b3;
                    ldsm4t(b0, b1, b2, b3, smWH + boffB + bb);
                    float* c = c16 + (fp << 3);
                    mma4(c, ah0, ah1, ah2, ah3, b0, b1);
                    mma4(c, al0, al1, al2, al3, b0, b1);
                    mma4(c + 4, ah0, ah1, ah2, ah3, b2, b3);
                    mma4(c + 4, al0, al1, al2, al3, b2, b3);
                }
            }
            #pragma unroll
            for (int f = 0; f < 4; f++) {
                int n = (s << 6) + (nh << 5) + (f << 3) + c2;
                float* c = c16 + ((f >> 1) << 3) + ((f & 1) << 2);
                #pragma unroll
                for (int e = 0; e < 4; e++) {
                    int nn = n + (e & 1);
                    const float* w = S.Vw1s[nn];
                    float z;
                    if (e < 2)
                        z = fmaf(xa0, w[0], fmaf(xa1, w[1], fmaf(xa2, w[2], fmaf(xa3, w[3], S.Vb1s[nn]))));
                    else
                        z = fmaf(xb0, w[0], fmaf(xb1, w[1], fmaf(xb2, w[2], fmaf(xb3, w[3], S.Vb1s[nn]))));
                    float a1v = tanhf(z);
                    float t = c[e] * (1.f - a1v * a1v);
                    float* gp = (e < 2) ? gpA : gpB;
                    gp[0] = fmaf(t, w[0], gp[0]);
                    gp[1] = fmaf(t, w[1], gp[1]);
                    gp[2] = fmaf(t, w[2], gp[2]);
                    gp[3] = fmaf(t, w[3], gp[3]);
                }
            }
        }
        #pragma unroll
        for (int j = 0; j < 4; j++) {
            gpA[j] += __shfl_xor_sync(0xffffffffu, gpA[j], 1);
            gpA[j] += __shfl_xor_sync(0xffffffffu, gpA[j], 2);
            gpB[j] += __shfl_xor_sync(0xffffffffu, gpB[j], 1);
            gpB[j] += __shfl_xor_sync(0xffffffffu, gpB[j], 2);
        }
        if ((lane & 3) == 0) {
            #pragma unroll
            for (int j = 0; j < 4; j++) {
                S.Gpart[rowAo][nh][j] = gpA[j];
                S.Gpart[rowBo][nh][j] = gpB[j];
            }
        }
    }

    // ==== G5: u1 planes + u2 GEMM + fold dot(Uw3) ====
    __syncthreads();
    layer1w(S, S.Uw1s, S.Ub1s, tid);
    {
        float acc[64];
        #pragma unroll
        for (int i = 0; i < 64; i++) acc[i] = 0.f;
        fwd256h(gUw2s, acc, S, smAH, smAL, smWH, tid, lane, nq, R0n);
        float pu[2][2] = {{0.f, 0.f}, {0.f, 0.f}};
        #pragma unroll
        for (int sub = 0; sub < 2; sub++) {
            #pragma unroll
            for (int fp = 0; fp < 4; fp++) {
                float* c = acc + (((sub << 2) + fp) << 3);
                #pragma unroll
                for (int h2 = 0; h2 < 2; h2++) {
                    int n = (nq << 6) + (fp << 4) + (h2 << 3) + c2;
                    pu[sub][0] = fmaf(tanhf(c[h2 * 4 + 0] + S.Ub2s[n]), S.Uw3s[n], pu[sub][0]);
                    pu[sub][0] = fmaf(tanhf(c[h2 * 4 + 1] + S.Ub2s[n + 1]), S.Uw3s[n + 1], pu[sub][0]);
                    pu[sub][1] = fmaf(tanhf(c[h2 * 4 + 2] + S.Ub2s[n]), S.Uw3s[n], pu[sub][1]);
                    pu[sub][1] = fmaf(tanhf(c[h2 * 4 + 3] + S.Ub2s[n + 1]), S.Uw3s[n + 1], pu[sub][1]);
                }
            }
            pu[sub][0] += __shfl_xor_sync(0xffffffffu, pu[sub][0], 1);
            pu[sub][0] += __shfl_xor_sync(0xffffffffu, pu[sub][0], 2);
            pu[sub][1] += __shfl_xor_sync(0xffffffffu, pu[sub][1], 1);
            pu[sub][1] += __shfl_xor_sync(0xffffffffu, pu[sub][1], 2);
            if ((lane & 3) == 0) {
                S.Upart[R0n + (sub << 4) + r4][nq] = pu[sub][0];
                S.Upart[R0n + (sub << 4) + r4 + 8][nq] = pu[sub][1];
            }
        }
    }
    __syncthreads();

    // ==== final per-row epilogue ====
    if (tid < CR) {
        int b = tid;
        float V = 0.5f * S.Vpart[b];
        float uu = S.Upart[b][0] + S.Upart[b][1] + S.Upart[b][2] + S.Upart[b][3];
        float u = 20.f * tanhf(uu + Ub3[0]);
        float gv0 = S.Gpart[b][0][0] + S.Gpart[b][1][0];
        float gv1 = S.Gpart[b][0][1] + S.Gpart[b][1][1];
        float gv2 = S.Gpart[b][0][2] + S.Gpart[b][1][2];
        float gv3 = S.Gpart[b][0][3] + S.Gpart[b][1][3];
        float th = S.X[b][1], v = S.X[b][2], om = S.X[b][3];
        float s, c;
        sincosf(th, &s, &c);
        float den1 = c - 24.7f, den2 = c * c - 24.7f;
        float f2 = (c * (9.8f * s + 11.5f * v) + 68.4f * v - 1.2f * om * om * s) / den1;
        float f3 = (-58.8f * v * c - 243.5f * v - s * (208.3f + om * om * c)) / den2;
        float g2 = (-1.8f * c - 10.9f) / den1;
        float g3 = (9.3f * c + 38.6f) / den2;
        float Lf = gv0 * v + gv1 * om + gv2 * f2 + gv3 * f3;
        float Lg = gv2 * g2 + gv3 * g3;
        int r = base + b;
        out[r] = u;
        out[BSZ + r] = V;
        out[2 * BSZ + r] = Lf + Lg * u;
    }
}

extern "C" void kernel_launch(void* const* d_in, const int* in_sizes, int n_in,
                              void* d_out, int out_size) {
    const float* x   = (const float*)d_in[0];
    const float* Vw1 = (const float*)d_in[1];
    const float* Vb1 = (const float*)d_in[2];
    const float* Vw2 = (const float*)d_in[3];
    const float* Vb2 = (const float*)d_in[4];
    const float* Vw3 = (const float*)d_in[5];
    const float* Vb3 = (const float*)d_in[6];
    const float* Uw1 = (const float*)d_in[7];
    const float* Ub1 = (const float*)d_in[8];
    const float* Uw2 = (const float*)d_in[9];
    const float* Ub2 = (const float*)d_in[10];
    const float* Uw3 = (const float*)d_in[11];
    const float* Ub3 = (const float*)d_in[12];
    float* out = (float*)d_out;

    prep_kernel<<<288, 512>>>(Vw2, Vw3, Uw2);
    cudaFuncSetAttribute(clf_mma, cudaFuncAttributeMaxDynamicSharedMemorySize,
                         (int)sizeof(Smem));
    clf_mma<<<BSZ / CR, NTH, sizeof(Smem)>>>(
        x, Vw1, Vb1, Vb2, Vb3, Uw1, Ub1, Ub2, Uw3, Ub3, out);
}